// round 1
// baseline (speedup 1.0000x reference)
#include <cuda_runtime.h>
#include <math_constants.h>

// Problem constants
#define BQ    2
#define NQ    8192
#define KNN   16
#define GROUP 8                      // threads cooperating on one query
#define QPB   16                     // queries per block
#define BLOCK 128                    // QPB * GROUP
#define TILE  2048                   // candidate points per smem tile
#define BLOCKS_PER_BATCH (NQ / QPB)  // 512
#define NBLK  ((BQ * NQ) / QPB)      // 1024 blocks total
#define TOTAL_EDGES ((double)(BQ) * (double)(NQ) * (double)(KNN))

// Deterministic per-block partial sums (no atomics -> same result every replay)
__device__ float g_partials[NBLK];

struct MergeSm {
    float md[QPB][GROUP][KNN];   // 8 KB
    int   mi[QPB][GROUP][KNN];   // 8 KB
    int   nbr[QPB][KNN];         // 1 KB
    float red[BLOCK];            // 0.5 KB
};

__global__ __launch_bounds__(BLOCK)
void knn_loss_kernel(const float* __restrict__ points_ref,
                     const float* __restrict__ points)
{
    __shared__ union {
        float4  tile[TILE];      // 32 KB  (x, y, z, sq) per candidate
        MergeSm mg;              // ~17.5 KB, reused after scan phase
    } sm;

    const int tid   = threadIdx.x;
    const int b     = blockIdx.x / BLOCKS_PER_BATCH;
    const int qbase = (blockIdx.x % BLOCKS_PER_BATCH) * QPB;
    const int ql    = tid / GROUP;       // query slot within block (0..15)
    const int g     = tid & (GROUP - 1); // lane within query group   (0..7)
    const int qn    = qbase + ql;        // query index within batch

    const float* __restrict__ pr = points_ref + (size_t)b * NQ * 3;
    const float* __restrict__ pp = points     + (size_t)b * NQ * 3;

    // Query point (ref cloud) + its squared norm, matching reference formula
    const float qx = pr[qn * 3 + 0];
    const float qy = pr[qn * 3 + 1];
    const float qz = pr[qn * 3 + 2];
    const float sqn = qx * qx + qy * qy + qz * qz;

    // Register-resident sorted top-16 (ascending d2), stable on ties by index
    float bd[KNN];
    int   bi[KNN];
#pragma unroll
    for (int j = 0; j < KNN; ++j) { bd[j] = CUDART_INF_F; bi[j] = -1; }

    // ---- KNN scan over the full cloud, tiled through shared memory ----
    for (int t0 = 0; t0 < NQ; t0 += TILE) {
        __syncthreads();
        // Cooperative tile load: 2048 points, 16 per thread. Precompute sq.
#pragma unroll
        for (int i = 0; i < TILE / BLOCK; ++i) {
            int   ml = tid + i * BLOCK;
            int   mi_g = t0 + ml;
            float x = pr[mi_g * 3 + 0];
            float y = pr[mi_g * 3 + 1];
            float z = pr[mi_g * 3 + 2];
            sm.tile[ml] = make_float4(x, y, z, x * x + y * y + z * z);
        }
        __syncthreads();

        // Each group lane scans its mod-8 residue class within the tile.
#pragma unroll 4
        for (int ml = g; ml < TILE; ml += GROUP) {
            float4 c   = sm.tile[ml];
            float  dot = qx * c.x + qy * c.y + qz * c.z;
            float  d2  = (sqn + c.w) - 2.0f * dot;   // same expansion as reference
            if (d2 < bd[KNN - 1]) {                  // rare path (~70/1024)
                int m = t0 + ml;
                if (m != qn) {                       // drop self (rank-0 in reference)
                    // stable insertion: equal keys keep earlier (lower) index first
#pragma unroll
                    for (int j = KNN - 1; j >= 0; --j) {
                        if (j == 0 || bd[j - 1] <= d2) {
                            bd[j] = d2; bi[j] = m;
                            break;
                        } else {
                            bd[j] = bd[j - 1]; bi[j] = bi[j - 1];
                        }
                    }
                }
            }
        }
    }

    __syncthreads();   // done with sm.tile; switch to merge layout

    // ---- Publish per-lane lists ----
#pragma unroll
    for (int j = 0; j < KNN; ++j) {
        sm.mg.md[ql][g][j] = bd[j];
        sm.mg.mi[ql][g][j] = bi[j];
    }
    __syncthreads();

    // ---- 8-way merge of sorted lists: one thread per query ----
    if (tid < QPB) {
        int head[GROUP];
#pragma unroll
        for (int gg = 0; gg < GROUP; ++gg) head[gg] = 0;
#pragma unroll 1
        for (int k = 0; k < KNN; ++k) {
            float best  = CUDART_INF_F;
            int   besti = 0x7fffffff;
            int   bg    = 0;
#pragma unroll
            for (int gg = 0; gg < GROUP; ++gg) {
                float d = sm.mg.md[tid][gg][head[gg]];
                int   i = sm.mg.mi[tid][gg][head[gg]];
                if (d < best || (d == best && i < besti)) {
                    best = d; besti = i; bg = gg;
                }
            }
#pragma unroll
            for (int gg = 0; gg < GROUP; ++gg)
                if (gg == bg) head[gg]++;
            sm.mg.nbr[tid][k] = besti;
        }
    }
    __syncthreads();

    // ---- Edge lengths + L1 accumulation: 2 edges per thread ----
    const float pqx = pp[qn * 3 + 0];
    const float pqy = pp[qn * 3 + 1];
    const float pqz = pp[qn * 3 + 2];

    float partial = 0.0f;
#pragma unroll
    for (int e = g; e < KNN; e += GROUP) {
        int nb = sm.mg.nbr[ql][e];
        float rx = pr[nb * 3 + 0] - qx;
        float ry = pr[nb * 3 + 1] - qy;
        float rz = pr[nb * 3 + 2] - qz;
        float dref = sqrtf(rx * rx + ry * ry + rz * rz);
        float px = pp[nb * 3 + 0] - pqx;
        float py = pp[nb * 3 + 1] - pqy;
        float pz = pp[nb * 3 + 2] - pqz;
        float dprd = sqrtf(px * px + py * py + pz * pz);
        partial += fabsf(dref - dprd);
    }

    // ---- Deterministic block reduction ----
    sm.mg.red[tid] = partial;
    __syncthreads();
#pragma unroll
    for (int s = BLOCK / 2; s > 0; s >>= 1) {
        if (tid < s) sm.mg.red[tid] += sm.mg.red[tid + s];
        __syncthreads();
    }
    if (tid == 0) g_partials[blockIdx.x] = sm.mg.red[0];
}

__global__ void finalize_kernel(float* __restrict__ out)
{
    __shared__ double sred[256];
    int t = threadIdx.x;
    double s = 0.0;
    for (int i = t; i < NBLK; i += 256) s += (double)g_partials[i];
    sred[t] = s;
    __syncthreads();
#pragma unroll
    for (int st = 128; st > 0; st >>= 1) {
        if (t < st) sred[t] += sred[t + st];
        __syncthreads();
    }
    if (t == 0) out[0] = (float)(sred[0] / TOTAL_EDGES);
}

extern "C" void kernel_launch(void* const* d_in, const int* in_sizes, int n_in,
                              void* d_out, int out_size)
{
    (void)in_sizes; (void)n_in; (void)out_size;
    const float* points_ref = (const float*)d_in[0];
    const float* points     = (const float*)d_in[1];
    knn_loss_kernel<<<NBLK, BLOCK>>>(points_ref, points);
    finalize_kernel<<<1, 256>>>((float*)d_out);
}

// round 3
// speedup vs baseline: 24.7170x; 24.7170x over previous
#include <cuda_runtime.h>
#include <math_constants.h>

// Problem constants
#define BQ    2
#define NQ    8192
#define KNN   16
#define WPB   16                       // warps (queries) per block
#define BLOCK (WPB * 32)               // 512 threads
#define TILE  2048                     // candidates per smem tile (32 KB of float4)
#define BLOCKS_PER_BATCH (NQ / WPB)    // 512
#define NBLK  (BQ * BLOCKS_PER_BATCH)  // 1024
#define FULL  0xffffffffu
#define TOTAL_EDGES ((double)(BQ) * (double)(NQ) * (double)(KNN))

// Deterministic per-block partial sums (no atomics -> same result every replay)
__device__ float g_partials[NBLK];

__global__ __launch_bounds__(BLOCK)
void knn_loss_kernel(const float* __restrict__ points_ref,
                     const float* __restrict__ points)
{
    __shared__ float4 tile[TILE];      // (x, y, z, x^2+y^2+z^2)
    __shared__ float  wsum[WPB];

    const int tid  = threadIdx.x;
    const int wid  = tid >> 5;
    const int lane = tid & 31;
    const int b    = blockIdx.x / BLOCKS_PER_BATCH;
    const int qn   = (blockIdx.x % BLOCKS_PER_BATCH) * WPB + wid;  // query for this warp

    const float* __restrict__ pr = points_ref + (size_t)b * NQ * 3;
    const float* __restrict__ pp = points     + (size_t)b * NQ * 3;

    // Query point (ref cloud) + squared norm (same expansion as reference)
    const float qx  = pr[qn * 3 + 0];
    const float qy  = pr[qn * 3 + 1];
    const float qz  = pr[qn * 3 + 2];
    const float sqn = qx * qx + qy * qy + qz * qz;

    // Warp-distributed sorted top-16: lane l (l<16) holds the (l+1)-th smallest.
    float kd  = CUDART_INF_F;   // keyed distance (d2)
    int   ki  = -1;             // candidate index
    float thr = CUDART_INF_F;   // current 16th-smallest (true warp-wide threshold)

    for (int t0 = 0; t0 < NQ; t0 += TILE) {
        __syncthreads();
        // Cooperative tile load: 2048 points, 4 per thread.
#pragma unroll
        for (int i = tid; i < TILE; i += BLOCK) {
            int   m = t0 + i;
            float x = pr[m * 3 + 0];
            float y = pr[m * 3 + 1];
            float z = pr[m * 3 + 2];
            tile[i] = make_float4(x, y, z, x * x + y * y + z * z);
        }
        __syncthreads();

        // Warp scans the whole tile, 32 candidates per step.
        for (int s = 0; s < TILE; s += 32) {
            const int    cand = t0 + s + lane;
            const float4 c    = tile[s + lane];
            float dot = fmaf(qx, c.x, fmaf(qy, c.y, qz * c.z));
            float d2  = fmaf(-2.0f, dot, sqn + c.w);   // sq_n + sq_m - 2*dot
            if (cand == qn) d2 = CUDART_INF_F;         // drop self (rank-0 in ref)

            unsigned mask = __ballot_sync(FULL, d2 < thr);
            while (mask) {
                // Lowest lane first == ascending candidate index (tie stability)
                const int   src = __ffs(mask) - 1;
                const float v   = __shfl_sync(FULL, d2,   src);
                const int   vi  = __shfl_sync(FULL, cand, src);

                // Insert position: after all existing elements <= v (existing
                // equals have lower index -> stable, matches top_k).
                const unsigned le  = __ballot_sync(FULL, (lane < KNN) && (kd <= v));
                const int      pos = __popc(le);       // 0..15 (v < kd[15] guaranteed)

                const float kdu = __shfl_up_sync(FULL, kd, 1);
                const int   kiu = __shfl_up_sync(FULL, ki, 1);
                kd = (lane < pos) ? kd : ((lane == pos) ? v  : kdu);
                ki = (lane < pos) ? ki : ((lane == pos) ? vi : kiu);

                thr  = __shfl_sync(FULL, kd, KNN - 1);
                mask &= ~(1u << src);
                mask &= __ballot_sync(FULL, d2 < thr); // re-filter vs tighter threshold
            }
        }
    }

    // ---- Edge lengths + L1: lanes 0..15 each handle one neighbor ----
    const float pqx = pp[qn * 3 + 0];
    const float pqy = pp[qn * 3 + 1];
    const float pqz = pp[qn * 3 + 2];

    float partial = 0.0f;
    if (lane < KNN) {
        const int nb  = ki;
        float rx = pr[nb * 3 + 0] - qx;
        float ry = pr[nb * 3 + 1] - qy;
        float rz = pr[nb * 3 + 2] - qz;
        float dref = sqrtf(rx * rx + ry * ry + rz * rz);
        float px = pp[nb * 3 + 0] - pqx;
        float py = pp[nb * 3 + 1] - pqy;
        float pz = pp[nb * 3 + 2] - pqz;
        float dprd = sqrtf(px * px + py * py + pz * pz);
        partial = fabsf(dref - dprd);
    }

    // Deterministic warp reduction (fixed shuffle order)
#pragma unroll
    for (int o = 16; o > 0; o >>= 1)
        partial += __shfl_xor_sync(FULL, partial, o);
    if (lane == 0) wsum[wid] = partial;
    __syncthreads();

    if (wid == 0) {
        float s = (lane < WPB) ? wsum[lane] : 0.0f;
#pragma unroll
        for (int o = 16; o > 0; o >>= 1)
            s += __shfl_xor_sync(FULL, s, o);
        if (lane == 0) g_partials[blockIdx.x] = s;
    }
}

__global__ void finalize_kernel(float* __restrict__ out)
{
    __shared__ double sred[256];
    int t = threadIdx.x;
    double s = 0.0;
    for (int i = t; i < NBLK; i += 256) s += (double)g_partials[i];
    sred[t] = s;
    __syncthreads();
#pragma unroll
    for (int st = 128; st > 0; st >>= 1) {
        if (t < st) sred[t] += sred[t + st];
        __syncthreads();
    }
    if (t == 0) out[0] = (float)(sred[0] / TOTAL_EDGES);
}

extern "C" void kernel_launch(void* const* d_in, const int* in_sizes, int n_in,
                              void* d_out, int out_size)
{
    (void)in_sizes; (void)n_in; (void)out_size;
    const float* points_ref = (const float*)d_in[0];
    const float* points     = (const float*)d_in[1];
    knn_loss_kernel<<<NBLK, BLOCK>>>(points_ref, points);
    finalize_kernel<<<1, 256>>>((float*)d_out);
}